// round 2
// baseline (speedup 1.0000x reference)
#include <cuda_runtime.h>
#include <math.h>

#define D       20
#define K1      30
#define KP      32          // padded K1
#define NRELP1  201
#define NTIME   365
#define NLAYERS 3
#define MAXN    1000000
#define EMAX    2000000

// ---------------- scratch (device globals; no runtime allocation) ----------------
__device__ __align__(16) float g_buf0[MAXN * D];            // 80 MB
__device__ __align__(16) float g_buf1[MAXN * D];            // 80 MB
__device__ __align__(16) float g_PbP[NRELP1 * KP];          // rela part of att MLP (padded)
__device__ __align__(16) float g_PcP[NRELP1 * KP];          // qrel part of att MLP (padded)
__device__ __align__(16) float g_RW[3 * NRELP1 * D];        // rela @ W_s^T
__device__ __align__(16) float g_TW[3 * NTIME * D];         // time @ W_s^T
__device__ __align__(16) float g_S0[NRELP1 * NRELP1];       // layer-0 sigmoid scores
// partition scratch: 3 regions, capacity EMAX each
__device__ __align__(16) int g_src2[3 * EMAX];
__device__ __align__(16) int g_dst2[3 * EMAX];
__device__ __align__(16) int g_rel2[3 * EMAX];
__device__ __align__(16) int g_qrel2[3 * EMAX];
__device__ __align__(16) int g_ta2[3 * EMAX];
__device__ int g_cnt[4];

// vectorized global float4 reduction (sm_90+)
__device__ __forceinline__ void red_add_v4(float* addr, float a, float b, float c, float d) {
    asm volatile(
        "{ .reg .u64 p; cvta.to.global.u64 p, %0;\n\t"
        "  red.global.add.v4.f32 [p], {%1, %2, %3, %4}; }\n\t"
        :: "l"(addr), "f"(a), "f"(b), "f"(c), "f"(d) : "memory");
}

__device__ __forceinline__ float leaky(float x) { return x > 0.f ? x : 0.01f * x; }

// ---------------- table precompute ----------------
__global__ void k_tables(const float* __restrict__ rela, const float* __restrict__ tem,
                         const float* __restrict__ w1,
                         const float* __restrict__ wp, const float* __restrict__ wn,
                         const float* __restrict__ wf)
{
    int i = blockIdx.x * blockDim.x + threadIdx.x;
    const int NPB = NRELP1 * KP;                 // 6432
    const int NRW = 3 * NRELP1 * D;              // 12060
    const int NTW = 3 * NTIME * D;               // 21900
    if (i < NPB) {                               // PbP[r][k] = rela[r] . w1[k][20:40]
        int r = i / KP, k = i % KP;
        float a = 0.f;
        if (k < K1) {
            #pragma unroll
            for (int j = 0; j < D; j++) a = fmaf(rela[r * D + j], w1[k * (3 * D) + D + j], a);
        }
        g_PbP[i] = a;
    } else if (i < 2 * NPB) {                    // PcP[r][k] = rela[r] . w1[k][40:60]
        int t = i - NPB;
        int r = t / KP, k = t % KP;
        float a = 0.f;
        if (k < K1) {
            #pragma unroll
            for (int j = 0; j < D; j++) a = fmaf(rela[r * D + j], w1[k * (3 * D) + 2 * D + j], a);
        }
        g_PcP[t] = a;
    } else if (i < 2 * NPB + NRW) {              // RW[s][r][o] = rela[r] . W_s[o]
        int t = i - 2 * NPB;
        int s = t / (NRELP1 * D);
        int rem = t % (NRELP1 * D);
        int r = rem / D, o = rem % D;
        const float* W = (s == 0) ? wp : ((s == 1) ? wn : wf);
        float a = 0.f;
        #pragma unroll
        for (int j = 0; j < D; j++) a = fmaf(rela[r * D + j], W[o * D + j], a);
        g_RW[t] = a;
    } else if (i < 2 * NPB + NRW + NTW) {        // TW[s][tt][o] = time[tt] . W_s[o]
        int t = i - 2 * NPB - NRW;
        int s = t / (NTIME * D);
        int rem = t % (NTIME * D);
        int tt = rem / D, o = rem % D;
        const float* W = (s == 0) ? wp : ((s == 1) ? wn : wf);
        float a = 0.f;
        #pragma unroll
        for (int j = 0; j < D; j++) a = fmaf(tem[tt * D + j], W[o * D + j], a);
        g_TW[t] = a;
    }
}

// layer-0 score table: h_src = 0 -> score depends only on (rel, qrel)
__global__ void k_s0(const float* __restrict__ w2)
{
    int i = blockIdx.x * blockDim.x + threadIdx.x;
    if (i >= NRELP1 * NRELP1) return;
    int r = i / NRELP1, q = i % NRELP1;
    float s = 0.f;
    #pragma unroll
    for (int k = 0; k < K1; k++) {
        float a = g_PbP[r * KP + k] + g_PcP[q * KP + k];
        a = fmaxf(a, 0.f);
        s = fmaf(a, w2[k], s);
    }
    g_S0[i] = 1.f / (1.f + __expf(-s));
}

// ---------------- 3-way partition by time branch ----------------
__global__ __launch_bounds__(256) void k_part(
    const int* __restrict__ src, const int* __restrict__ dst,
    const int* __restrict__ rel, const int* __restrict__ qrel,
    const int* __restrict__ rtime, int E)
{
    int e = blockIdx.x * blockDim.x + threadIdx.x;
    bool valid = e < E;
    int sel = 3, ta = 0, s = 0, d = 0, r = 0, q = 0;
    if (valid) {
        s = src[e]; d = dst[e]; r = rel[e]; q = qrel[e];
        int t = rtime[e];
        sel = (t > 0) ? 2 : ((t == 0) ? 1 : 0);
        ta = t < 0 ? -t : t;
    }
    int lane = threadIdx.x & 31;
    #pragma unroll
    for (int rr = 0; rr < 3; rr++) {
        unsigned m = __ballot_sync(0xffffffffu, valid && sel == rr);
        if (m) {
            int leader = __ffs(m) - 1;
            int base = 0;
            if (lane == leader) base = atomicAdd(&g_cnt[rr], __popc(m));
            base = __shfl_sync(0xffffffffu, base, leader);
            if (valid && sel == rr) {
                int pos = base + __popc(m & ((1u << lane) - 1u));
                int o = rr * EMAX + pos;
                g_src2[o] = s; g_dst2[o] = d; g_rel2[o] = r;
                g_qrel2[o] = q; g_ta2[o] = ta;
            }
        }
    }
}

// ---------------- layer 0: hidden == 0, pure gather/scale/scatter (4 edges/thread) ----
__global__ __launch_bounds__(256) void k_edge0(
    const int* __restrict__ dst, const int* __restrict__ rel,
    const int* __restrict__ qrel, const int* __restrict__ rtime,
    float* __restrict__ hout, int E)
{
    int e4 = (blockIdx.x * blockDim.x + threadIdx.x) * 4;
    if (e4 >= E) return;                 // E % 4 == 0
    int4 d4 = *(const int4*)(dst + e4);
    int4 r4 = *(const int4*)(rel + e4);
    int4 q4 = *(const int4*)(qrel + e4);
    int4 t4 = *(const int4*)(rtime + e4);
    int dn[4] = {d4.x, d4.y, d4.z, d4.w};
    int rl[4] = {r4.x, r4.y, r4.z, r4.w};
    int ql[4] = {q4.x, q4.y, q4.z, q4.w};
    int tt[4] = {t4.x, t4.y, t4.z, t4.w};
    float score[4];
    const float4* rwp[4];
    const float4* twp[4];
    float* outp[4];
    #pragma unroll
    for (int e = 0; e < 4; e++) {
        int t = tt[e];
        int sel = (t > 0) ? 2 : ((t == 0) ? 1 : 0);
        int ta = t < 0 ? -t : t;
        score[e] = g_S0[rl[e] * NRELP1 + ql[e]];
        rwp[e] = (const float4*)(g_RW + (sel * NRELP1 + rl[e]) * D);
        twp[e] = (const float4*)(g_TW + (sel * NTIME + ta) * D);
        outp[e] = hout + (size_t)dn[e] * D;
    }
    #pragma unroll
    for (int g = 0; g < D / 4; g++) {
        #pragma unroll
        for (int e = 0; e < 4; e++) {
            float4 a = rwp[e][g];
            float4 b = twp[e][g];
            float sc = score[e];
            red_add_v4(outp[e] + 4 * g,
                       sc * (a.x + b.x), sc * (a.y + b.y),
                       sc * (a.z + b.z), sc * (a.w + b.w));
        }
    }
}

// ---------------- generic layer: partitioned, 4 edges/thread ----------------
__global__ __launch_bounds__(256) void k_edge4(
    const float* __restrict__ hin, float* __restrict__ hout,
    const float* __restrict__ w1, const float* __restrict__ w2,
    const float* __restrict__ wp, const float* __restrict__ wn,
    const float* __restrict__ wf)
{
    __shared__ __align__(16) float sw1a[KP * D];   // w_att1[:, 0:20], rows 30/31 zero
    __shared__ float sw2s[KP];
    __shared__ __align__(16) float sW[3 * D * D];  // past / now / future
    for (int i = threadIdx.x; i < KP * D; i += blockDim.x) {
        int k = i / D, j = i % D;
        sw1a[i] = (k < K1) ? w1[k * (3 * D) + j] : 0.f;
    }
    for (int i = threadIdx.x; i < KP; i += blockDim.x)
        sw2s[i] = (i < K1) ? w2[i] : 0.f;
    for (int i = threadIdx.x; i < 3 * D * D; i += blockDim.x) {
        int s = i / (D * D); int rem = i % (D * D);
        sW[i] = ((s == 0) ? wp : ((s == 1) ? wn : wf))[rem];
    }
    __syncthreads();

    long long vt = (long long)blockIdx.x * blockDim.x + threadIdx.x;
    long long e4 = vt * 4;
    if (e4 >= 3LL * EMAX) return;
    int rgn = (int)(e4 / EMAX);                     // EMAX % 4 == 0 -> batch stays in region
    int local = (int)(e4 - (long long)rgn * EMAX);
    int cnt = g_cnt[rgn];
    if (local >= cnt) return;

    int o = rgn * EMAX + local;                     // 16B aligned
    int4 s4 = *(const int4*)(g_src2 + o);
    int4 d4 = *(const int4*)(g_dst2 + o);
    int4 r4 = *(const int4*)(g_rel2 + o);
    int4 q4 = *(const int4*)(g_qrel2 + o);
    int4 t4 = *(const int4*)(g_ta2 + o);
    int sn[4] = {s4.x, s4.y, s4.z, s4.w};
    int dn[4] = {d4.x, d4.y, d4.z, d4.w};
    int rl[4] = {r4.x, r4.y, r4.z, r4.w};
    int ql[4] = {q4.x, q4.y, q4.z, q4.w};
    int ta[4] = {t4.x, t4.y, t4.z, t4.w};

    // gather + fused leaky_relu
    float h[4][D];
    #pragma unroll
    for (int e = 0; e < 4; e++) {
        const float4* hp = (const float4*)(hin + (size_t)sn[e] * D);
        #pragma unroll
        for (int i = 0; i < D / 4; i++) {
            float4 v = hp[i];
            h[e][4 * i + 0] = leaky(v.x);
            h[e][4 * i + 1] = leaky(v.y);
            h[e][4 * i + 2] = leaky(v.z);
            h[e][4 * i + 3] = leaky(v.w);
        }
    }

    // attention: a_k = h . w1a_k + Pb[rel][k] + Pc[qrel][k]; score = sigmoid(relu(a) . w2)
    float sacc[4] = {0.f, 0.f, 0.f, 0.f};
    {
        const float4* pbp[4];
        const float4* pcp[4];
        #pragma unroll
        for (int e = 0; e < 4; e++) {
            pbp[e] = (const float4*)(g_PbP + rl[e] * KP);
            pcp[e] = (const float4*)(g_PcP + ql[e] * KP);
        }
        #pragma unroll
        for (int g = 0; g < KP / 4; g++) {
            float4 pb4[4], pc4[4];
            #pragma unroll
            for (int e = 0; e < 4; e++) { pb4[e] = pbp[e][g]; pc4[e] = pcp[e][g]; }
            #pragma unroll
            for (int c = 0; c < 4; c++) {
                int k = g * 4 + c;
                const float4* wr = (const float4*)(sw1a + k * D);
                float w[D];
                #pragma unroll
                for (int i = 0; i < D / 4; i++) {
                    float4 v = wr[i];
                    w[4 * i + 0] = v.x; w[4 * i + 1] = v.y;
                    w[4 * i + 2] = v.z; w[4 * i + 3] = v.w;
                }
                float w2k = sw2s[k];
                #pragma unroll
                for (int e = 0; e < 4; e++) {
                    float a = ((const float*)&pb4[e])[c] + ((const float*)&pc4[e])[c];
                    #pragma unroll
                    for (int j = 0; j < D; j++) a = fmaf(h[e][j], w[j], a);
                    sacc[e] = fmaf(fmaxf(a, 0.f), w2k, sacc[e]);
                }
            }
        }
    }
    float score[4];
    #pragma unroll
    for (int e = 0; e < 4; e++) {
        score[e] = 1.f / (1.f + __expf(-sacc[e]));
        if (local + e >= cnt) score[e] = 0.f;   // tail edges read zero-filled slots -> no-op add
    }

    // transformed = h @ W_rgn^T + RW + TW ; msg = score * transformed; scatter
    const float* Wb = sW + rgn * D * D;
    const float4* rwp[4];
    const float4* twp[4];
    float* outp[4];
    #pragma unroll
    for (int e = 0; e < 4; e++) {
        rwp[e] = (const float4*)(g_RW + (rgn * NRELP1 + rl[e]) * D);
        twp[e] = (const float4*)(g_TW + (rgn * NTIME + ta[e]) * D);
        outp[e] = hout + (size_t)dn[e] * D;
    }
    #pragma unroll
    for (int g = 0; g < D / 4; g++) {
        float4 rt[4];
        #pragma unroll
        for (int e = 0; e < 4; e++) {
            float4 a = rwp[e][g];
            float4 b = twp[e][g];
            rt[e] = make_float4(a.x + b.x, a.y + b.y, a.z + b.z, a.w + b.w);
        }
        float mv[4][4];
        #pragma unroll
        for (int c = 0; c < 4; c++) {
            int i = g * 4 + c;
            const float4* wr = (const float4*)(Wb + i * D);
            float w[D];
            #pragma unroll
            for (int ii = 0; ii < D / 4; ii++) {
                float4 v = wr[ii];
                w[4 * ii + 0] = v.x; w[4 * ii + 1] = v.y;
                w[4 * ii + 2] = v.z; w[4 * ii + 3] = v.w;
            }
            #pragma unroll
            for (int e = 0; e < 4; e++) {
                float acc = ((const float*)&rt[e])[c];
                #pragma unroll
                for (int j = 0; j < D; j++) acc = fmaf(h[e][j], w[j], acc);
                mv[e][c] = score[e] * acc;
            }
        }
        #pragma unroll
        for (int e = 0; e < 4; e++)
            red_add_v4(outp[e] + 4 * g, mv[e][0], mv[e][1], mv[e][2], mv[e][3]);
    }
}

// ---------------- final: leaky -> dot(w_cls) + b -> scatter ----------------
__global__ __launch_bounds__(256) void k_final(
    const float* __restrict__ hin, const int* __restrict__ nb,
    const int* __restrict__ ne, const float* __restrict__ wcls,
    const float* __restrict__ bcls, const int* __restrict__ pne,
    float* __restrict__ out, int n)
{
    int i = blockIdx.x * blockDim.x + threadIdx.x;
    if (i >= n) return;
    const float4* hp = (const float4*)(hin + (size_t)i * D);
    float acc = bcls[0];
    #pragma unroll
    for (int g = 0; g < D / 4; g++) {
        float4 v = hp[g];
        acc = fmaf(leaky(v.x), __ldg(wcls + 4 * g + 0), acc);
        acc = fmaf(leaky(v.y), __ldg(wcls + 4 * g + 1), acc);
        acc = fmaf(leaky(v.z), __ldg(wcls + 4 * g + 2), acc);
        acc = fmaf(leaky(v.w), __ldg(wcls + 4 * g + 3), acc);
    }
    long long idx = (long long)nb[i] * (long long)pne[0] + (long long)ne[i];
    out[idx] = acc;
}

// ---------------- host ----------------
extern "C" void kernel_launch(void* const* d_in, const int* in_sizes, int n_in,
                              void* d_out, int out_size)
{
    const int*   src   = (const int*)d_in[0];
    const int*   dst   = (const int*)d_in[1];
    const int*   rel   = (const int*)d_in[2];
    const int*   qrel  = (const int*)d_in[3];
    const int*   rtime = (const int*)d_in[4];
    const int*   nb    = (const int*)d_in[5];
    const int*   ne    = (const int*)d_in[6];
    const float* rela  = (const float*)d_in[7];
    const float* tem   = (const float*)d_in[8];
    const float* w1    = (const float*)d_in[9];
    const float* w2    = (const float*)d_in[10];
    const float* wp    = (const float*)d_in[11];
    const float* wn    = (const float*)d_in[12];
    const float* wf    = (const float*)d_in[13];
    const float* wcls  = (const float*)d_in[14];
    const float* bcls  = (const float*)d_in[15];
    const int*   pne   = (const int*)d_in[17];

    int E  = in_sizes[0] / NLAYERS;
    int Nn = in_sizes[5];

    float *b0, *b1;
    int *cntp;
    cudaGetSymbolAddress((void**)&b0, g_buf0);
    cudaGetSymbolAddress((void**)&b1, g_buf1);
    cudaGetSymbolAddress((void**)&cntp, g_cnt);
    size_t bufBytes = (size_t)Nn * D * sizeof(float);

    // precompute tables (independent of hidden state)
    const int NTAB = 2 * NRELP1 * KP + 3 * NRELP1 * D + 3 * NTIME * D;
    k_tables<<<(NTAB + 255) / 256, 256>>>(rela, tem, w1, wp, wn, wf);
    k_s0<<<(NRELP1 * NRELP1 + 255) / 256, 256>>>(w2);

    int gE  = (E + 255) / 256;
    int gE4 = (E / 4 + 255) / 256;
    int gP4 = (int)((3LL * EMAX / 4 + 255) / 256);

    // layer 0 (h = 0): accumulate into buf1
    cudaMemsetAsync(b1, 0, bufBytes);
    k_edge0<<<gE4, 256>>>(dst, rel, qrel, rtime, b1, E);

    // layer 1: partition, then read act(buf1) -> accumulate buf0
    cudaMemsetAsync(cntp, 0, 4 * sizeof(int));
    k_part<<<gE, 256>>>(src + E, dst + E, rel + E, qrel + E, rtime + E, E);
    cudaMemsetAsync(b0, 0, bufBytes);
    k_edge4<<<gP4, 256>>>(b1, b0, w1, w2, wp, wn, wf);

    // layer 2: partition, then read act(buf0) -> accumulate buf1
    cudaMemsetAsync(cntp, 0, 4 * sizeof(int));
    k_part<<<gE, 256>>>(src + 2 * E, dst + 2 * E, rel + 2 * E, qrel + 2 * E, rtime + 2 * E, E);
    cudaMemsetAsync(b1, 0, bufBytes);
    k_edge4<<<gP4, 256>>>(b0, b1, w1, w2, wp, wn, wf);

    // output: zero then scatter
    cudaMemsetAsync(d_out, 0, (size_t)out_size * sizeof(float));
    k_final<<<(Nn + 255) / 256, 256>>>(b1, nb, ne, wcls, bcls, pne, (float*)d_out, Nn);
}